// round 7
// baseline (speedup 1.0000x reference)
#include <cuda_runtime.h>
#include <cuda_fp16.h>
#include <cstdint>

#define NN 21
#define D 256
#define GH 512
#define NE 40
#define NB 8192
#define M_TOTAL (NB * NN)      /* 172032 */
#define NCAT 1280
#define LN_EPS 1e-5f

#define BPC 6                  /* batch elems per CTA */
#define ROWSV (BPC * NN)       /* 126 valid rows */
#define MTILE 128
#define NBLK ((NB + BPC - 1) / BPC)   /* 1366 */

#define NTC 256                /* N chunk */
#define NNC (NCAT / NTC)       /* 5 */
#define KC 32
#define NITER (NNC * (D / KC)) /* 40 */

#define A_STRH 264
#define B_STRH 40
#define ST_STRH 132

/* smem byte offsets */
#define OFF_A   0
#define SZ_A    (MTILE * A_STRH * 2)        /* 67584 */
#define OFF_B   (OFF_A + SZ_A)
#define SZ_B    (2 * NTC * B_STRH * 2)      /* 40960 */
#define OFF_ST  (OFF_B + SZ_B)
#define SZ_ST   (2 * 128 * ST_STRH * 2)     /* 67584: two half-col buffers */
#define OFF_W2  (OFF_ST + SZ_ST)
#define SZ_W2   (GH * 4)
#define OFF_GA  (OFF_W2 + SZ_W2)
#define SZ_GA   (BPC * NE * 4)              /* 960 */
#define OFF_IDX (OFF_GA + SZ_GA + 64)
#define FUSED_SMEM (OFF_IDX + 1024)         /* ~176 KB */

// ---------------- scratch ----------------
__device__ __half g_V[(size_t)M_TOTAL * D];      /* V part only, fp16 */
__device__ __half g_WcatT[(size_t)NCAT * D];     /* interleaved [n][k] K-major */
__device__ float  g_bias[NCAT];
__device__ int    g_bStart[NN + 1];
__device__ int    g_bEdge[NE];

// ---------------- helpers ----------------
__device__ __forceinline__ void cp_async16(void* smem, const void* gmem) {
    unsigned s = (unsigned)__cvta_generic_to_shared(smem);
    asm volatile("cp.async.cg.shared.global [%0], [%1], 16;\n" :: "r"(s), "l"(gmem));
}
__device__ __forceinline__ float gelu1(float t) {
    return 0.5f * t * (1.f + erff(t * 0.7071067811865476f));
}
__device__ __forceinline__ void mma16(float* d, const unsigned* a, const unsigned* b) {
    asm volatile(
        "mma.sync.aligned.m16n8k16.row.col.f32.f16.f16.f32 "
        "{%0,%1,%2,%3}, {%4,%5,%6,%7}, {%8,%9}, {%0,%1,%2,%3};\n"
        : "+f"(d[0]), "+f"(d[1]), "+f"(d[2]), "+f"(d[3])
        : "r"(a[0]), "r"(a[1]), "r"(a[2]), "r"(a[3]), "r"(b[0]), "r"(b[1]));
}

// ---------------- kernel 0: interleaved weights + bias + edge buckets ----------------
/* col n: n<256 -> V (Wv[:,n], bias bv[n]);
   n>=256: j=(n-256)>>1; even -> A_j = W1[0:256][j], bias b1[j]; odd -> B_j = W1[256:512][j], bias 0 */
__global__ void prep_kernel(const float* __restrict__ Wv, const float* __restrict__ bv,
                            const float* __restrict__ W1, const float* __restrict__ b1,
                            const int* __restrict__ srcI, const int* __restrict__ dstI) {
    int idx = blockIdx.x * blockDim.x + threadIdx.x;
    if (idx < D * NCAT) {
        int k = idx / NCAT, n = idx % NCAT;
        float w;
        if (n < 256) w = Wv[k * 256 + n];
        else {
            int m = n - 256, j = m >> 1;
            w = (m & 1) ? W1[(256 + k) * 512 + j] : W1[k * 512 + j];
        }
        g_WcatT[(size_t)n * D + k] = __float2half_rn(w);
    }
    if (idx < NCAT) {
        float bb;
        if (idx < 256) bb = bv[idx];
        else { int m = idx - 256; bb = (m & 1) ? 0.f : b1[m >> 1]; }
        g_bias[idx] = bb;
    }
    if (blockIdx.x == 0 && threadIdx.x == 0) {
        int cnt[NN];
        for (int n = 0; n < NN; n++) cnt[n] = 0;
        for (int e = 0; e < NE; e++) cnt[dstI[e]]++;
        g_bStart[0] = 0;
        for (int n = 0; n < NN; n++) g_bStart[n + 1] = g_bStart[n] + cnt[n];
        int pos[NN];
        for (int n = 0; n < NN; n++) pos[n] = g_bStart[n];
        for (int e = 0; e < NE; e++) g_bEdge[pos[dstI[e]]++] = e;
    }
}

// ---------------- fused kernel ----------------
__device__ __forceinline__ void load_B_stage(__half* Bst, int tid, int idx) {
    int nb = (idx >> 3) * NTC, kb = (idx & 7) * KC;
    #pragma unroll
    for (int t = 0; t < 4; t++) {
        int ch = tid + (t << 8);
        int row = ch >> 2, c8 = (ch & 3) * 8;
        cp_async16((char*)Bst + row * (B_STRH * 2) + c8 * 2,
                   g_WcatT + (size_t)(nb + row) * D + kb + c8);
    }
    asm volatile("cp.async.commit_group;\n");
}

__global__ __launch_bounds__(256, 1) void fused_kernel(
    const float* __restrict__ h, const int* __restrict__ srcI, const int* __restrict__ dstI,
    const float* __restrict__ lnw, const float* __restrict__ lnb,
    const float* __restrict__ W2, const float* __restrict__ b2, float* __restrict__ out) {
    extern __shared__ __align__(16) char smem[];
    __half* sA  = (__half*)(smem + OFF_A);
    __half* sB  = (__half*)(smem + OFF_B);
    __half* sSt = (__half*)(smem + OFF_ST);   /* [buf][128][ST_STRH] halves */
    float*  sW2 = (float*)(smem + OFF_W2);
    float*  sGA = (float*)(smem + OFF_GA);
    int* sSrc = (int*)(smem + OFF_IDX);
    int* sDst = sSrc + NE;
    int* sBS  = sDst + NE;
    int* sBE  = sBS + NN + 1;

    const int tid = threadIdx.x, warp = tid >> 5, lane = tid & 31;
    const int wm = warp & 1, wn = warp >> 1;
    const int g = lane >> 2, t = lane & 3;
    const int mBase = blockIdx.x * ROWSV;
    const int valid = min(BPC, NB - blockIdx.x * BPC);
    const int rowLim = valid * NN;            /* global+local bound for this CTA */

    if (tid < NE) { sSrc[tid] = srcI[tid]; sDst[tid] = dstI[tid]; sBE[tid] = g_bEdge[tid]; }
    if (tid >= 64 && tid < 64 + NN + 1) sBS[tid - 64] = g_bStart[tid - 64];
    if (tid < 128) ((float4*)sW2)[tid] = ((const float4*)W2)[tid];
    if (tid < BPC * NE) sGA[tid] = 0.f;

    load_B_stage(sB, tid, 0);
    load_B_stage(sB + NTC * B_STRH, tid, 1);

    /* ---- fused LayerNorm: warp per row, fp16 into sA ---- */
    {
        float4 w0 = ((const float4*)lnw)[2 * lane], w1 = ((const float4*)lnw)[2 * lane + 1];
        float4 bb0 = ((const float4*)lnb)[2 * lane], bb1 = ((const float4*)lnb)[2 * lane + 1];
        #pragma unroll 1
        for (int it = 0; it < 16; it++) {
            int row = it * 8 + warp;
            int gRow = mBase + row; if (gRow > M_TOTAL - 1) gRow = M_TOTAL - 1;
            const float4* r4 = (const float4*)(h + (size_t)gRow * D);
            float4 va = r4[2 * lane], vb = r4[2 * lane + 1];
            float s = va.x + va.y + va.z + va.w + vb.x + vb.y + vb.z + vb.w;
            float q = va.x*va.x + va.y*va.y + va.z*va.z + va.w*va.w
                    + vb.x*vb.x + vb.y*vb.y + vb.z*vb.z + vb.w*vb.w;
            #pragma unroll
            for (int off = 16; off; off >>= 1) {
                s += __shfl_xor_sync(0xffffffffu, s, off);
                q += __shfl_xor_sync(0xffffffffu, q, off);
            }
            float mu = s * (1.f / D);
            float var = q * (1.f / D) - mu * mu;
            float inv = rsqrtf(var + LN_EPS);
            __half2 h0 = __floats2half2_rn((va.x - mu) * inv * w0.x + bb0.x,
                                           (va.y - mu) * inv * w0.y + bb0.y);
            __half2 h1 = __floats2half2_rn((va.z - mu) * inv * w0.z + bb0.z,
                                           (va.w - mu) * inv * w0.w + bb0.w);
            __half2 h2 = __floats2half2_rn((vb.x - mu) * inv * w1.x + bb1.x,
                                           (vb.y - mu) * inv * w1.y + bb1.y);
            __half2 h3 = __floats2half2_rn((vb.z - mu) * inv * w1.z + bb1.z,
                                           (vb.w - mu) * inv * w1.w + bb1.w);
            uint4 o;
            o.x = *(unsigned*)&h0; o.y = *(unsigned*)&h1;
            o.z = *(unsigned*)&h2; o.w = *(unsigned*)&h3;
            *(uint4*)(sA + row * A_STRH + lane * 8) = o;
        }
    }
    __syncthreads();

    /* ---- main loop: mma + interleaved gate slices ---- */
    float c[4][8][4];
    for (int i = 0; i < NITER; i++) {
        int chunk = i >> 3, kc = i & 7;
        if (kc == 0) {
            #pragma unroll
            for (int mi = 0; mi < 4; mi++)
                #pragma unroll
                for (int ni = 0; ni < 8; ni++)
                    #pragma unroll
                    for (int j = 0; j < 4; j++) c[mi][ni][j] = 0.f;
        }
        if (i < NITER - 2) asm volatile("cp.async.wait_group 1;\n" ::: "memory");
        else               asm volatile("cp.async.wait_group 0;\n" ::: "memory");
        __syncthreads();
        const __half* Bst = sB + (i & 1) * NTC * B_STRH;
        #pragma unroll
        for (int ks = 0; ks < 2; ks++) {
            unsigned af[4][4], bf[8][2];
            int kabs = kc * KC + ks * 16 + 2 * t;
            int krel = ks * 16 + 2 * t;
            #pragma unroll
            for (int mi = 0; mi < 4; mi++) {
                int rb = wm * 64 + mi * 16 + g;
                af[mi][0] = *(const unsigned*)(sA + rb * A_STRH + kabs);
                af[mi][1] = *(const unsigned*)(sA + (rb + 8) * A_STRH + kabs);
                af[mi][2] = *(const unsigned*)(sA + rb * A_STRH + kabs + 8);
                af[mi][3] = *(const unsigned*)(sA + (rb + 8) * A_STRH + kabs + 8);
            }
            #pragma unroll
            for (int ni = 0; ni < 8; ni++) {
                int nr = wn * 64 + ni * 8 + g;
                bf[ni][0] = *(const unsigned*)(Bst + nr * B_STRH + krel);
                bf[ni][1] = *(const unsigned*)(Bst + nr * B_STRH + krel + 8);
            }
            #pragma unroll
            for (int mi = 0; mi < 4; mi++)
                #pragma unroll
                for (int ni = 0; ni < 8; ni++)
                    mma16(c[mi][ni], af[mi], bf[ni]);
        }

        /* gate slice for staged data-chunk (chunk-1): pairs jg = (chunk-2)*128 + j */
        if (chunk >= 2 && kc < 6) {
            int jgB = (chunk - 2) * 128;
            int kk1 = min(kc * 5 + 5, 30);
            #pragma unroll 1
            for (int kk = kc * 5; kk < kk1; kk++) {
                int combo = warp + (kk << 3);
                int be = combo / NE, e = combo - be * NE;
                int sR = be * NN + sSrc[e], dR = be * NN + sDst[e];
                float sum = 0.f;
                #pragma unroll
                for (int rep = 0; rep < 4; rep++) {
                    int j = lane + (rep << 5);
                    int colL = j << 1;
                    int boff = (colL >> 7) * 128;
                    __half2 a2 = *(const __half2*)(sSt + (boff + sR) * ST_STRH + (colL & 127));
                    __half2 d2 = *(const __half2*)(sSt + (boff + dR) * ST_STRH + (colL & 127));
                    float tt = __low2float(a2) + __high2float(d2);
                    sum += gelu1(tt) * sW2[jgB + j];
                }
                #pragma unroll
                for (int off = 16; off; off >>= 1) sum += __shfl_xor_sync(0xffffffffu, sum, off);
                if (!lane) sGA[combo] += sum;
            }
        }
        __syncthreads();
        if (i + 2 < NITER) load_B_stage(sB + (i & 1) * NTC * B_STRH, tid, i + 2);

        if (kc == 7) {
            if (chunk == 0) {          /* V chunk -> gmem (fp16, +bias), rowLim predicate */
                #pragma unroll
                for (int mi = 0; mi < 4; mi++)
                    #pragma unroll
                    for (int ni = 0; ni < 8; ni++) {
                        int r0 = wm * 64 + mi * 16 + g;
                        int c0 = wn * 64 + ni * 8 + 2 * t;
                        float b0v = g_bias[c0], b1v = g_bias[c0 + 1];
                        if (r0 < rowLim)
                            *(__half2*)(g_V + (size_t)(mBase + r0) * D + c0) =
                                __floats2half2_rn(c[mi][ni][0] + b0v, c[mi][ni][1] + b1v);
                        if (r0 + 8 < rowLim)
                            *(__half2*)(g_V + (size_t)(mBase + r0 + 8) * D + c0) =
                                __floats2half2_rn(c[mi][ni][2] + b0v, c[mi][ni][3] + b1v);
                    }
            } else {                   /* stage A/B pairs (+bias) into smem */
                #pragma unroll
                for (int mi = 0; mi < 4; mi++)
                    #pragma unroll
                    for (int ni = 0; ni < 8; ni++) {
                        int r0 = wm * 64 + mi * 16 + g;
                        int colL = wn * 64 + ni * 8 + 2 * t;
                        int gcol = chunk * 256 + colL;
                        float b0v = g_bias[gcol], b1v = g_bias[gcol + 1];
                        __half* p = sSt + ((colL >> 7) * 128 + r0) * ST_STRH + (colL & 127);
                        *(__half2*)p = __floats2half2_rn(c[mi][ni][0] + b0v, c[mi][ni][1] + b1v);
                        *(__half2*)(p + 8 * ST_STRH) =
                            __floats2half2_rn(c[mi][ni][2] + b0v, c[mi][ni][3] + b1v);
                    }
            }
        }
    }

    /* ---- tail: gate for last staged chunk (data chunk 4, jg base 384) ---- */
    __syncthreads();
    {
        #pragma unroll 1
        for (int kk = 0; kk < 30; kk++) {
            int combo = warp + (kk << 3);
            int be = combo / NE, e = combo - be * NE;
            int sR = be * NN + sSrc[e], dR = be * NN + sDst[e];
            float sum = 0.f;
            #pragma unroll
            for (int rep = 0; rep < 4; rep++) {
                int j = lane + (rep << 5);
                int colL = j << 1;
                int boff = (colL >> 7) * 128;
                __half2 a2 = *(const __half2*)(sSt + (boff + sR) * ST_STRH + (colL & 127));
                __half2 d2 = *(const __half2*)(sSt + (boff + dR) * ST_STRH + (colL & 127));
                float tt = __low2float(a2) + __high2float(d2);
                sum += gelu1(tt) * sW2[384 + j];
            }
            #pragma unroll
            for (int off = 16; off; off >>= 1) sum += __shfl_xor_sync(0xffffffffu, sum, off);
            if (!lane) sGA[combo] += sum;
        }
    }
    __syncthreads();
    if (tid < BPC * NE) sGA[tid] = 1.f / (1.f + __expf(-(sGA[tid] + __ldg(b2))));
    __syncthreads();

    /* ---- scatter + residual: thread = column ---- */
    #pragma unroll 1
    for (int be = 0; be < valid; be++) {
        #pragma unroll 1
        for (int n = 0; n < NN; n++) {
            int r = be * NN + n;
            float acc = h[(size_t)(mBase + r) * D + tid];
            int jEnd = sBS[n + 1];
            for (int jj = sBS[n]; jj < jEnd; jj++) {
                int e = sBE[jj];
                acc += sGA[be * NE + e] *
                       __half2float(g_V[(size_t)(mBase + be * NN + sSrc[e]) * D + tid]);
            }
            out[(size_t)(mBase + r) * D + tid] = acc;
        }
    }
}

// ---------------- launcher ----------------
extern "C" void kernel_launch(void* const* d_in, const int* in_sizes, int n_in,
                              void* d_out, int out_size) {
    const float* h    = (const float*)d_in[0];
    const int*   srcI = (const int*)d_in[1];
    const int*   dstI = (const int*)d_in[2];
    const float* ln_w = (const float*)d_in[3];
    const float* ln_b = (const float*)d_in[4];
    const float* Wv   = (const float*)d_in[5];
    const float* bv   = (const float*)d_in[6];
    const float* W1   = (const float*)d_in[7];
    const float* b1   = (const float*)d_in[8];
    const float* W2   = (const float*)d_in[9];
    const float* b2   = (const float*)d_in[10];
    float* out = (float*)d_out;

    cudaFuncSetAttribute(fused_kernel, cudaFuncAttributeMaxDynamicSharedMemorySize, FUSED_SMEM);

    prep_kernel<<<(D * NCAT + 255) / 256, 256>>>(Wv, bv, W1, b1, srcI, dstI);
    fused_kernel<<<NBLK, 256, FUSED_SMEM>>>(h, srcI, dstI, ln_w, ln_b, W2, b2, out);
}

// round 8
// speedup vs baseline: 1.5834x; 1.5834x over previous
#include <cuda_runtime.h>
#include <cuda_fp16.h>
#include <cstdint>

#define NN 21
#define D 256
#define GH 512
#define NE 40
#define NB 8192
#define M_TOTAL (NB * NN)     /* 172032 */
#define NCAT 1280
#define LN_EPS 1e-5f

#define MT 128                /* M per CTA */
#define NTC 256               /* N chunk */
#define KC 32                 /* K per B stage */
#define NITER 40              /* 5 chunks x 8 k-steps */

#define A_STRH 264            /* halves */
#define B_STRH 40             /* halves */
#define B_STAGE_H (NTC * B_STRH)
#define SZ_A (MT * A_STRH * 2)                   /* 67584 B */
#define GEMM_SMEM (SZ_A + 3 * B_STAGE_H * 2)     /* 129024 B */

#define EBPC 2                /* batches per edge CTA */

// ---------------- scratch ----------------
__device__ __half g_Y[(size_t)M_TOTAL * NCAT];
__device__ __half g_WcatT[(size_t)NCAT * D];   /* [n][k] K-major; V|A|B blocks */
__device__ float  g_bias[NCAT];
__device__ int    g_bStart[NN + 1];
__device__ int    g_bEdge[NE];

// ---------------- helpers ----------------
__device__ __forceinline__ void cp_async16(void* smem, const void* gmem) {
    unsigned s = (unsigned)__cvta_generic_to_shared(smem);
    asm volatile("cp.async.cg.shared.global [%0], [%1], 16;\n" :: "r"(s), "l"(gmem));
}
__device__ __forceinline__ float gelu1(float t) {
    return 0.5f * t * (1.f + erff(t * 0.7071067811865476f));
}
__device__ __forceinline__ void mma16(float* d, const unsigned* a, const unsigned* b) {
    asm volatile(
        "mma.sync.aligned.m16n8k16.row.col.f32.f16.f16.f32 "
        "{%0,%1,%2,%3}, {%4,%5,%6,%7}, {%8,%9}, {%0,%1,%2,%3};\n"
        : "+f"(d[0]), "+f"(d[1]), "+f"(d[2]), "+f"(d[3])
        : "r"(a[0]), "r"(a[1]), "r"(a[2]), "r"(a[3]), "r"(b[0]), "r"(b[1]));
}
__device__ __forceinline__ void ldsm4(unsigned* r, uint32_t addr) {
    asm volatile("ldmatrix.sync.aligned.m8n8.x4.shared.b16 {%0,%1,%2,%3}, [%4];"
        : "=r"(r[0]), "=r"(r[1]), "=r"(r[2]), "=r"(r[3]) : "r"(addr));
}

// ---------------- kernel 0: weights concat (fp16, K-major) + bias + buckets ----------------
__global__ void prep_kernel(const float* __restrict__ Wv, const float* __restrict__ bv,
                            const float* __restrict__ W1, const float* __restrict__ b1,
                            const int* __restrict__ srcI, const int* __restrict__ dstI) {
    int idx = blockIdx.x * blockDim.x + threadIdx.x;
    if (idx < D * NCAT) {
        int k = idx / NCAT, n = idx % NCAT;
        float w;
        if (n < 256)      w = Wv[k * 256 + n];
        else if (n < 768) w = W1[k * 512 + (n - 256)];
        else              w = W1[(256 + k) * 512 + (n - 768)];
        g_WcatT[(size_t)n * D + k] = __float2half_rn(w);
    }
    if (idx < NCAT)
        g_bias[idx] = (idx < 256) ? bv[idx] : (idx < 768 ? b1[idx - 256] : 0.f);
    if (blockIdx.x == 0 && threadIdx.x == 0) {
        int cnt[NN];
        for (int n = 0; n < NN; n++) cnt[n] = 0;
        for (int e = 0; e < NE; e++) cnt[dstI[e]]++;
        g_bStart[0] = 0;
        for (int n = 0; n < NN; n++) g_bStart[n + 1] = g_bStart[n] + cnt[n];
        int pos[NN];
        for (int n = 0; n < NN; n++) pos[n] = g_bStart[n];
        for (int e = 0; e < NE; e++) g_bEdge[pos[dstI[e]]++] = e;
    }
}

// ---------------- kernel 1: fused LN + fp16 GEMM (512 thr, ldmatrix) ----------------
__device__ __forceinline__ void load_B_stage(__half* sB, int tid, int idx) {
    int nb = (idx >> 3) * NTC, kb = (idx & 7) * KC;
    __half* Bst = sB + (idx % 3) * B_STAGE_H;
    #pragma unroll
    for (int t = 0; t < 2; t++) {                 /* 1024 x 16B chunks / 512 thr */
        int ch = tid + (t << 9);
        int row = ch >> 2, c8 = (ch & 3) * 8;
        cp_async16((char*)Bst + row * (B_STRH * 2) + c8 * 2,
                   g_WcatT + (size_t)(nb + row) * D + kb + c8);
    }
    asm volatile("cp.async.commit_group;\n");
}

__global__ __launch_bounds__(512, 1) void gemm_ln_kernel(
    const float* __restrict__ h, const float* __restrict__ lnw, const float* __restrict__ lnb) {
    extern __shared__ __align__(16) char smem[];
    __half* sA = (__half*)smem;                         /* [MT][A_STRH] */
    __half* sB = (__half*)(smem + SZ_A);                /* 3 stages */
    const int tid = threadIdx.x, warp = tid >> 5, lane = tid & 31;
    const int wm = warp & 3, wn = warp >> 2;            /* warp tile 32x64 */
    const int g = lane >> 3 ? 0 : 0;                    /* placeholder */
    const int gq = lane >> 2, t = lane & 3;
    const int mBase = blockIdx.x * MT;
    const uint32_t sAu = (uint32_t)__cvta_generic_to_shared(sA);
    const uint32_t sBu = (uint32_t)__cvta_generic_to_shared(sB);

    load_B_stage(sB, tid, 0);
    load_B_stage(sB, tid, 1);

    /* ---- fused LayerNorm: warp per row ---- */
    {
        float4 w0 = ((const float4*)lnw)[2 * lane], w1 = ((const float4*)lnw)[2 * lane + 1];
        float4 bb0 = ((const float4*)lnb)[2 * lane], bb1 = ((const float4*)lnb)[2 * lane + 1];
        #pragma unroll 1
        for (int it = 0; it < 8; it++) {
            int row = warp * 8 + it;
            const float4* r4 = (const float4*)(h + (size_t)(mBase + row) * D);
            float4 va = r4[2 * lane], vb = r4[2 * lane + 1];
            float s = va.x + va.y + va.z + va.w + vb.x + vb.y + vb.z + vb.w;
            float q = va.x*va.x + va.y*va.y + va.z*va.z + va.w*va.w
                    + vb.x*vb.x + vb.y*vb.y + vb.z*vb.z + vb.w*vb.w;
            #pragma unroll
            for (int off = 16; off; off >>= 1) {
                s += __shfl_xor_sync(0xffffffffu, s, off);
                q += __shfl_xor_sync(0xffffffffu, q, off);
            }
            float mu = s * (1.f / D);
            float var = q * (1.f / D) - mu * mu;
            float inv = rsqrtf(var + LN_EPS);
            __half2 h0 = __floats2half2_rn((va.x - mu) * inv * w0.x + bb0.x,
                                           (va.y - mu) * inv * w0.y + bb0.y);
            __half2 h1 = __floats2half2_rn((va.z - mu) * inv * w0.z + bb0.z,
                                           (va.w - mu) * inv * w0.w + bb0.w);
            __half2 h2 = __floats2half2_rn((vb.x - mu) * inv * w1.x + bb1.x,
                                           (vb.y - mu) * inv * w1.y + bb1.y);
            __half2 h3 = __floats2half2_rn((vb.z - mu) * inv * w1.z + bb1.z,
                                           (vb.w - mu) * inv * w1.w + bb1.w);
            uint4 o;
            o.x = *(unsigned*)&h0; o.y = *(unsigned*)&h1;
            o.z = *(unsigned*)&h2; o.w = *(unsigned*)&h3;
            *(uint4*)(sA + row * A_STRH + lane * 8) = o;
        }
    }
    __syncthreads();

    /* per-lane ldmatrix base addresses (bytes) */
    const int lm = lane >> 3, lr = lane & 7;
    uint32_t aBase[2], bOff[4];
    #pragma unroll
    for (int mi = 0; mi < 2; mi++)
        aBase[mi] = sAu + (uint32_t)(((wm * 32 + mi * 16 + (lm & 1) * 8 + lr) * A_STRH
                                      + (lm >> 1) * 8) * 2);
    #pragma unroll
    for (int nj = 0; nj < 4; nj++)
        bOff[nj] = (uint32_t)(((wn * 64 + nj * 16 + (lm >> 1) * 8 + lr) * B_STRH
                               + (lm & 1) * 8) * 2);

    float c[2][8][4];
    for (int i = 0; i < NITER; i++) {
        int chunk = i >> 3, kc = i & 7;
        if (kc == 0) {
            #pragma unroll
            for (int mi = 0; mi < 2; mi++)
                #pragma unroll
                for (int ni = 0; ni < 8; ni++)
                    #pragma unroll
                    for (int j = 0; j < 4; j++) c[mi][ni][j] = 0.f;
        }
        if (i < NITER - 2) asm volatile("cp.async.wait_group 1;\n" ::: "memory");
        else               asm volatile("cp.async.wait_group 0;\n" ::: "memory");
        __syncthreads();
        if (i + 2 < NITER) load_B_stage(sB, tid, i + 2);

        uint32_t stB = sBu + (uint32_t)((i % 3) * B_STAGE_H * 2);
        #pragma unroll
        for (int ks = 0; ks < 2; ks++) {
            unsigned af[2][4], bf[4][4];
            uint32_t ka = (uint32_t)((kc * KC + ks * 16) * 2);
            uint32_t kb = (uint32_t)((ks * 16) * 2);
            ldsm4(af[0], aBase[0] + ka);
            ldsm4(af[1], aBase[1] + ka);
            ldsm4(bf[0], stB + bOff[0] + kb);
            ldsm4(bf[1], stB + bOff[1] + kb);
            ldsm4(bf[2], stB + bOff[2] + kb);
            ldsm4(bf[3], stB + bOff[3] + kb);
            /* bf[nj] = { (n-blk 2nj: k0-7, k8-15), (n-blk 2nj+1: k0-7, k8-15) } */
            #pragma unroll
            for (int mi = 0; mi < 2; mi++)
                #pragma unroll
                for (int nj = 0; nj < 4; nj++) {
                    mma16(c[mi][2 * nj],     af[mi], &bf[nj][0]);
                    mma16(c[mi][2 * nj + 1], af[mi], &bf[nj][2]);
                }
        }

        if (kc == 7) {         /* epilogue: bias + fp16 store */
            int nBase = chunk * NTC;
            #pragma unroll
            for (int mi = 0; mi < 2; mi++)
                #pragma unroll
                for (int ni = 0; ni < 8; ni++) {
                    int r0 = mBase + wm * 32 + mi * 16 + gq;
                    int c0 = nBase + wn * 64 + ni * 8 + 2 * t;
                    float b0v = g_bias[c0], b1v = g_bias[c0 + 1];
                    *(__half2*)(g_Y + (size_t)r0 * NCAT + c0) =
                        __floats2half2_rn(c[mi][ni][0] + b0v, c[mi][ni][1] + b1v);
                    *(__half2*)(g_Y + (size_t)(r0 + 8) * NCAT + c0) =
                        __floats2half2_rn(c[mi][ni][2] + b0v, c[mi][ni][3] + b1v);
                }
        }
    }
}

// ---------------- kernel 2: gates + bucketed scatter + residual (2 batches/CTA) ----------------
__global__ __launch_bounds__(512) void edge_kernel(const float* __restrict__ h,
                                                   const int* __restrict__ srcI,
                                                   const int* __restrict__ dstI,
                                                   const float* __restrict__ W2,
                                                   const float* __restrict__ b2,
                                                   float* __restrict__ out) {
    __shared__ __half sV[EBPC * NN * D];   /* 21 KB */
    __shared__ float  sGate[EBPC * NE];
    __shared__ float  sW2[GH];
    __shared__ int sSrc[NE], sDst[NE], sBS[NN + 1], sBE[NE];
    int b0 = blockIdx.x * EBPC;
    int tid = threadIdx.x;
    if (tid < NE) { sSrc[tid] = srcI[tid]; sDst[tid] = dstI[tid]; sBE[tid] = g_bEdge[tid]; }
    if (tid >= 64 && tid < 64 + NN + 1) sBS[tid - 64] = g_bStart[tid - 64];
    if (tid >= 128 && tid < 256) ((float4*)sW2)[tid - 128] = ((const float4*)W2)[tid - 128];
    const __half* Yb = g_Y + (size_t)b0 * NN * NCAT;
    #pragma unroll 1
    for (int i = tid; i < EBPC * NN * 32; i += 512) {     /* V parts, uint4 */
        int r = i >> 5, cc = i & 31;                      /* r = be*NN+n */
        ((uint4*)sV)[i] = ((const uint4*)(Yb + ((r / NN) * NN * NCAT) + (r % NN) * NCAT))[cc];
    }
    __syncthreads();

    int warp = tid >> 5, lane = tid & 31;
    float b2v = __ldg(b2);
    #pragma unroll 1
    for (int kk = 0; kk < 5; kk++) {
        int combo = warp + (kk << 4);                     /* 0..79 */
        int be = combo / NE, e = combo - be * NE;
        const __half* Yr = Yb + (size_t)be * NN * NCAT;
        const uint4* A4 = (const uint4*)(Yr + sSrc[e] * NCAT + 256);
        const uint4* B4 = (const uint4*)(Yr + sDst[e] * NCAT + 768);
        float sum = 0.f;
        #pragma unroll
        for (int i = lane; i < 64; i += 32) {
            uint4 ua = __ldg(A4 + i), ub = __ldg(B4 + i);
            const float* wv = sW2 + i * 8;
            float2 a0 = __half22float2(*(__half2*)&ua.x), d0 = __half22float2(*(__half2*)&ub.x);
            float2 a1 = __half22float2(*(__half2*)&ua.y), d1 = __half22float2(*(__half2*)&ub.y);
            float2 a2 = __half22float2(*(__half2*)&ua.z), d2 = __half22float2(*(__half2*)&ub.z);
            float2 a3 = __half22float2(*(__half2*)&ua.w), d3 = __half22float2(*(__half2*)&ub.w);
            sum += gelu1(a0.x + d0.x) * wv[0] + gelu1(a0.y + d0.y) * wv[1];
            sum += gelu1(a1.x + d1.x) * wv[2] + gelu1(a1.y + d1.y) * wv[3];
            sum += gelu1(a2.x + d2.x) * wv[4] + gelu1(a2.y + d2.y) * wv[5];
            sum += gelu1(a3.x + d3.x) * wv[6] + gelu1(a3.y + d3.y) * wv[7];
        }
        #pragma unroll
        for (int off = 16; off; off >>= 1) sum += __shfl_xor_sync(0xffffffffu, sum, off);
        if (!lane) sGate[combo] = 1.f / (1.f + __expf(-(sum + b2v)));
    }
    __syncthreads();

    const float* hb = h + (size_t)b0 * NN * D;
    float* ob = out + (size_t)b0 * NN * D;
    int col = tid & 63, slot = tid >> 6;                  /* 8 row-slots */
    #pragma unroll 1
    for (int task = slot; task < EBPC * NN; task += 8) {
        int be = task / NN, n = task - be * NN;
        int r = be * NN + n;
        float4 acc = ((const float4*)(hb + r * D))[col];
        int jEnd = sBS[n + 1];
        for (int jj = sBS[n]; jj < jEnd; jj++) {
            int e = sBE[jj];
            float gte = sGate[be * NE + e];
            uint2 u = *(const uint2*)(sV + (be * NN + sSrc[e]) * D + col * 4);
            float2 lo = __half22float2(*(__half2*)&u.x);
            float2 hi = __half22float2(*(__half2*)&u.y);
            acc.x += gte * lo.x; acc.y += gte * lo.y;
            acc.z += gte * hi.x; acc.w += gte * hi.y;
        }
        ((float4*)(ob + r * D))[col] = acc;
    }
}

// ---------------- launcher ----------------
extern "C" void kernel_launch(void* const* d_in, const int* in_sizes, int n_in,
                              void* d_out, int out_size) {
    const float* h    = (const float*)d_in[0];
    const int*   srcI = (const int*)d_in[1];
    const int*   dstI = (const int*)d_in[2];
    const float* ln_w = (const float*)d_in[3];
    const float* ln_b = (const float*)d_in[4];
    const float* Wv   = (const float*)d_in[5];
    const float* bv   = (const float*)d_in[6];
    const float* W1   = (const float*)d_in[7];
    const float* b1   = (const float*)d_in[8];
    const float* W2   = (const float*)d_in[9];
    const float* b2   = (const float*)d_in[10];
    float* out = (float*)d_out;

    cudaFuncSetAttribute(gemm_ln_kernel, cudaFuncAttributeMaxDynamicSharedMemorySize, GEMM_SMEM);

    prep_kernel<<<(D * NCAT + 255) / 256, 256>>>(Wv, bv, W1, b1, srcI, dstI);
    gemm_ln_kernel<<<M_TOTAL / MT, 512, GEMM_SMEM>>>(h, ln_w, ln_b);
    edge_kernel<<<NB / EBPC, 512>>>(h, srcI, dstI, W2, b2, out);
}

// round 9
// speedup vs baseline: 1.6712x; 1.0555x over previous
#include <cuda_runtime.h>
#include <cuda_fp16.h>
#include <cstdint>

#define NN 21
#define D 256
#define GH 512
#define NE 40
#define NB 8192
#define M_TOTAL (NB * NN)     /* 172032 */
#define NCAT 1280
#define LN_EPS 1e-5f

#define MT 64                 /* M per CTA (2 CTAs per SM) */
#define NTC 256               /* N chunk */
#define KC 64                 /* K per B stage */
#define NITER 20              /* 5 chunks x 4 k-steps */

#define A_STRH 264            /* halves: 528B/row, bank shift 4 -> conflict-free ldsm */
#define B_STRH 72             /* halves: 144B/row, bank shift 4 -> conflict-free ldsm */
#define B_STAGE_H (NTC * B_STRH)
#define SZ_A (MT * A_STRH * 2)                   /* 33792 B */
#define GEMM_SMEM (SZ_A + 2 * B_STAGE_H * 2)     /* 107520 B -> 2 CTAs/SM */

#define EBPC 2                /* batches per edge CTA */

// ---------------- scratch ----------------
__device__ __half g_Y[(size_t)M_TOTAL * NCAT];
__device__ __half g_WcatT[(size_t)NCAT * D];   /* [n][k] K-major; V|A|B blocks */
__device__ float  g_bias[NCAT];
__device__ int    g_bStart[NN + 1];
__device__ int    g_bEdge[NE];

// ---------------- helpers ----------------
__device__ __forceinline__ void cp_async16(void* smem, const void* gmem) {
    unsigned s = (unsigned)__cvta_generic_to_shared(smem);
    asm volatile("cp.async.cg.shared.global [%0], [%1], 16;\n" :: "r"(s), "l"(gmem));
}
__device__ __forceinline__ float gelu1(float t) {
    return 0.5f * t * (1.f + erff(t * 0.7071067811865476f));
}
__device__ __forceinline__ void mma16(float* d, const unsigned* a, const unsigned* b) {
    asm volatile(
        "mma.sync.aligned.m16n8k16.row.col.f32.f16.f16.f32 "
        "{%0,%1,%2,%3}, {%4,%5,%6,%7}, {%8,%9}, {%0,%1,%2,%3};\n"
        : "+f"(d[0]), "+f"(d[1]), "+f"(d[2]), "+f"(d[3])
        : "r"(a[0]), "r"(a[1]), "r"(a[2]), "r"(a[3]), "r"(b[0]), "r"(b[1]));
}
__device__ __forceinline__ void ldsm4(unsigned* r, uint32_t addr) {
    asm volatile("ldmatrix.sync.aligned.m8n8.x4.shared.b16 {%0,%1,%2,%3}, [%4];"
        : "=r"(r[0]), "=r"(r[1]), "=r"(r[2]), "=r"(r[3]) : "r"(addr));
}

// ---------------- kernel 0: weights concat (fp16, K-major) + bias + buckets ----------------
__global__ void prep_kernel(const float* __restrict__ Wv, const float* __restrict__ bv,
                            const float* __restrict__ W1, const float* __restrict__ b1,
                            const int* __restrict__ srcI, const int* __restrict__ dstI) {
    int idx = blockIdx.x * blockDim.x + threadIdx.x;
    if (idx < D * NCAT) {
        int k = idx / NCAT, n = idx % NCAT;
        float w;
        if (n < 256)      w = Wv[k * 256 + n];
        else if (n < 768) w = W1[k * 512 + (n - 256)];
        else              w = W1[(256 + k) * 512 + (n - 768)];
        g_WcatT[(size_t)n * D + k] = __float2half_rn(w);
    }
    if (idx < NCAT)
        g_bias[idx] = (idx < 256) ? bv[idx] : (idx < 768 ? b1[idx - 256] : 0.f);
    if (blockIdx.x == 0 && threadIdx.x == 0) {
        int cnt[NN];
        for (int n = 0; n < NN; n++) cnt[n] = 0;
        for (int e = 0; e < NE; e++) cnt[dstI[e]]++;
        g_bStart[0] = 0;
        for (int n = 0; n < NN; n++) g_bStart[n + 1] = g_bStart[n] + cnt[n];
        int pos[NN];
        for (int n = 0; n < NN; n++) pos[n] = g_bStart[n];
        for (int e = 0; e < NE; e++) g_bEdge[pos[dstI[e]]++] = e;
    }
}

// ---------------- kernel 1: fused LN + fp16 GEMM (256 thr, 2 CTAs/SM) ----------------
__device__ __forceinline__ void load_B_stage(__half* sB, int tid, int idx) {
    int nb = (idx >> 2) * NTC, kb = (idx & 3) * KC;
    __half* Bst = sB + (idx & 1) * B_STAGE_H;
    #pragma unroll
    for (int t = 0; t < 8; t++) {                 /* 2048 x 16B chunks / 256 thr */
        int ch = tid + (t << 8);
        int row = ch >> 3, c8 = (ch & 7) * 8;
        cp_async16((char*)Bst + row * (B_STRH * 2) + c8 * 2,
                   g_WcatT + (size_t)(nb + row) * D + kb + c8);
    }
    asm volatile("cp.async.commit_group;\n");
}

__global__ __launch_bounds__(256, 2) void gemm_ln_kernel(
    const float* __restrict__ h, const float* __restrict__ lnw, const float* __restrict__ lnb) {
    extern __shared__ __align__(16) char smem[];
    __half* sA = (__half*)smem;                         /* [MT][A_STRH] */
    __half* sB = (__half*)(smem + SZ_A);                /* 2 stages */
    const int tid = threadIdx.x, warp = tid >> 5, lane = tid & 31;
    const int wm = warp & 1, wn = warp >> 1;            /* 2x4 warps, tile 32x64 */
    const int gq = lane >> 2, t = lane & 3;
    const int mBase = blockIdx.x * MT;
    const uint32_t sAu = (uint32_t)__cvta_generic_to_shared(sA);
    const uint32_t sBu = (uint32_t)__cvta_generic_to_shared(sB);

    load_B_stage(sB, tid, 0);

    /* ---- fused LayerNorm: warp per row, 8 rows/warp ---- */
    {
        float4 w0 = ((const float4*)lnw)[2 * lane], w1 = ((const float4*)lnw)[2 * lane + 1];
        float4 bb0 = ((const float4*)lnb)[2 * lane], bb1 = ((const float4*)lnb)[2 * lane + 1];
        #pragma unroll 1
        for (int it = 0; it < 8; it++) {
            int row = warp * 8 + it;
            const float4* r4 = (const float4*)(h + (size_t)(mBase + row) * D);
            float4 va = r4[2 * lane], vb = r4[2 * lane + 1];
            float s = va.x + va.y + va.z + va.w + vb.x + vb.y + vb.z + vb.w;
            float q = va.x*va.x + va.y*va.y + va.z*va.z + va.w*va.w
                    + vb.x*vb.x + vb.y*vb.y + vb.z*vb.z + vb.w*vb.w;
            #pragma unroll
            for (int off = 16; off; off >>= 1) {
                s += __shfl_xor_sync(0xffffffffu, s, off);
                q += __shfl_xor_sync(0xffffffffu, q, off);
            }
            float mu = s * (1.f / D);
            float var = q * (1.f / D) - mu * mu;
            float inv = rsqrtf(var + LN_EPS);
            __half2 h0 = __floats2half2_rn((va.x - mu) * inv * w0.x + bb0.x,
                                           (va.y - mu) * inv * w0.y + bb0.y);
            __half2 h1 = __floats2half2_rn((va.z - mu) * inv * w0.z + bb0.z,
                                           (va.w - mu) * inv * w0.w + bb0.w);
            __half2 h2 = __floats2half2_rn((vb.x - mu) * inv * w1.x + bb1.x,
                                           (vb.y - mu) * inv * w1.y + bb1.y);
            __half2 h3 = __floats2half2_rn((vb.z - mu) * inv * w1.z + bb1.z,
                                           (vb.w - mu) * inv * w1.w + bb1.w);
            uint4 o;
            o.x = *(unsigned*)&h0; o.y = *(unsigned*)&h1;
            o.z = *(unsigned*)&h2; o.w = *(unsigned*)&h3;
            *(uint4*)(sA + row * A_STRH + lane * 8) = o;
        }
    }
    __syncthreads();

    /* per-lane ldmatrix base addresses (bytes) */
    const int lm = lane >> 3, lr = lane & 7;
    uint32_t aBase[2], bOff[4];
    #pragma unroll
    for (int mi = 0; mi < 2; mi++)
        aBase[mi] = sAu + (uint32_t)(((wm * 32 + mi * 16 + (lm & 1) * 8 + lr) * A_STRH
                                      + (lm >> 1) * 8) * 2);
    #pragma unroll
    for (int nj = 0; nj < 4; nj++)
        bOff[nj] = (uint32_t)(((wn * 64 + nj * 16 + (lm >> 1) * 8 + lr) * B_STRH
                               + (lm & 1) * 8) * 2);

    float c[2][8][4];
    for (int i = 0; i < NITER; i++) {
        int chunk = i >> 2, kc = i & 3;
        if (kc == 0) {
            #pragma unroll
            for (int mi = 0; mi < 2; mi++)
                #pragma unroll
                for (int ni = 0; ni < 8; ni++)
                    #pragma unroll
                    for (int j = 0; j < 4; j++) c[mi][ni][j] = 0.f;
        }
        if (i + 1 < NITER) {                 /* prefetch next stage a full iter ahead */
            load_B_stage(sB, tid, i + 1);
            asm volatile("cp.async.wait_group 1;\n" ::: "memory");
        } else {
            asm volatile("cp.async.wait_group 0;\n" ::: "memory");
        }
        __syncthreads();

        uint32_t stB = sBu + (uint32_t)((i & 1) * B_STAGE_H * 2);
        #pragma unroll
        for (int ks = 0; ks < 4; ks++) {
            unsigned af[2][4], bf[4][4];
            uint32_t ka = (uint32_t)((kc * KC + ks * 16) * 2);
            uint32_t kb = (uint32_t)((ks * 16) * 2);
            ldsm4(af[0], aBase[0] + ka);
            ldsm4(af[1], aBase[1] + ka);
            ldsm4(bf[0], stB + bOff[0] + kb);
            ldsm4(bf[1], stB + bOff[1] + kb);
            ldsm4(bf[2], stB + bOff[2] + kb);
            ldsm4(bf[3], stB + bOff[3] + kb);
            #pragma unroll
            for (int mi = 0; mi < 2; mi++)
                #pragma unroll
                for (int nj = 0; nj < 4; nj++) {
                    mma16(c[mi][2 * nj],     af[mi], &bf[nj][0]);
                    mma16(c[mi][2 * nj + 1], af[mi], &bf[nj][2]);
                }
        }

        if (kc == 3) {         /* epilogue: bias + fp16 store */
            int nBase = chunk * NTC;
            #pragma unroll
            for (int mi = 0; mi < 2; mi++)
                #pragma unroll
                for (int ni = 0; ni < 8; ni++) {
                    int r0 = mBase + wm * 32 + mi * 16 + gq;
                    int c0 = nBase + wn * 64 + ni * 8 + 2 * t;
                    float b0v = g_bias[c0], b1v = g_bias[c0 + 1];
                    *(__half2*)(g_Y + (size_t)r0 * NCAT + c0) =
                        __floats2half2_rn(c[mi][ni][0] + b0v, c[mi][ni][1] + b1v);
                    *(__half2*)(g_Y + (size_t)(r0 + 8) * NCAT + c0) =
                        __floats2half2_rn(c[mi][ni][2] + b0v, c[mi][ni][3] + b1v);
                }
        }
        __syncthreads();       /* compute done before next prefetch reuses buffer */
    }
}

// ---------------- kernel 2: gates + bucketed scatter + residual (2 batches/CTA) ----------------
__global__ __launch_bounds__(512) void edge_kernel(const float* __restrict__ h,
                                                   const int* __restrict__ srcI,
                                                   const int* __restrict__ dstI,
                                                   const float* __restrict__ W2,
                                                   const float* __restrict__ b2,
                                                   float* __restrict__ out) {
    __shared__ __half sV[EBPC * NN * D];   /* 21 KB */
    __shared__ float  sGate[EBPC * NE];
    __shared__ float  sW2[GH];
    __shared__ int sSrc[NE], sDst[NE], sBS[NN + 1], sBE[NE];
    int b0 = blockIdx.x * EBPC;
    int tid = threadIdx.x;
    if (tid < NE) { sSrc[tid] = srcI[tid]; sDst[tid] = dstI[tid]; sBE[tid] = g_bEdge[tid]; }
    if (tid >= 64 && tid < 64 + NN + 1) sBS[tid - 64] = g_bStart[tid - 64];
    if (tid >= 128 && tid < 256) ((float4*)sW2)[tid - 128] = ((const float4*)W2)[tid - 128];
    const __half* Yb = g_Y + (size_t)b0 * NN * NCAT;
    #pragma unroll 1
    for (int i = tid; i < EBPC * NN * 32; i += 512) {     /* V parts, uint4 */
        int r = i >> 5, cc = i & 31;
        ((uint4*)sV)[i] = ((const uint4*)(Yb + ((r / NN) * NN * NCAT) + (r % NN) * NCAT))[cc];
    }
    __syncthreads();

    int warp = tid >> 5, lane = tid & 31;
    float b2v = __ldg(b2);
    #pragma unroll 1
    for (int kk = 0; kk < 5; kk++) {
        int combo = warp + (kk << 4);                     /* 0..79 */
        int be = combo / NE, e = combo - be * NE;
        const __half* Yr = Yb + (size_t)be * NN * NCAT;
        const uint4* A4 = (const uint4*)(Yr + sSrc[e] * NCAT + 256);
        const uint4* B4 = (const uint4*)(Yr + sDst[e] * NCAT + 768);
        float sum = 0.f;
        #pragma unroll
        for (int i = lane; i < 64; i += 32) {
            uint4 ua = __ldg(A4 + i), ub = __ldg(B4 + i);
            const float* wv = sW2 + i * 8;
            float2 a0 = __half22float2(*(__half2*)&ua.x), d0 = __half22float2(*(__half2*)&ub.x);
            float2 a1 = __half22float2(*(__half2*)&ua.y), d1 = __half22float2(*(__half2*)&ub.y);
            float2 a2 = __half22float2(*(__half2*)&ua.z), d2 = __half22float2(*(__half2*)&ub.z);
            float2 a3 = __half22float2(*(__half2*)&ua.w), d3 = __half22float2(*(__half2*)&ub.w);
            sum += gelu1(a0.x + d0.x) * wv[0] + gelu1(a0.y + d0.y) * wv[1];
            sum += gelu1(a1.x + d1.x) * wv[2] + gelu1(a1.y + d1.y) * wv[3];
            sum += gelu1(a2.x + d2.x) * wv[4] + gelu1(a2.y + d2.y) * wv[5];
            sum += gelu1(a3.x + d3.x) * wv[6] + gelu1(a3.y + d3.y) * wv[7];
        }
        #pragma unroll
        for (int off = 16; off; off >>= 1) sum += __shfl_xor_sync(0xffffffffu, sum, off);
        if (!lane) sGate[combo] = 1.f / (1.f + __expf(-(sum + b2v)));
    }
    __syncthreads();

    const float* hb = h + (size_t)b0 * NN * D;
    float* ob = out + (size_t)b0 * NN * D;
    int col = tid & 63, slot = tid >> 6;                  /* 8 row-slots */
    #pragma unroll 1
    for (int task = slot; task < EBPC * NN; task += 8) {
        int be = task / NN, n = task - be * NN;
        int r = be * NN + n;
        float4 acc = ((const float4*)(hb + r * D))[col];
        int jEnd = sBS[n + 1];
        for (int jj = sBS[n]; jj < jEnd; jj++) {
            int e = sBE[jj];
            float gte = sGate[be * NE + e];
            uint2 u = *(const uint2*)(sV + (be * NN + sSrc[e]) * D + col * 4);
            float2 lo = __half22float2(*(__half2*)&u.x);
            float2 hi = __half22float2(*(__half2*)&u.y);
            acc.x += gte * lo.x; acc.y += gte * lo.y;
            acc.z += gte * hi.x; acc.w += gte * hi.y;
        }
        ((float4*)(ob + r * D))[col] = acc;
    }
}

// ---------------- launcher ----------------
extern "C" void kernel_launch(void* const* d_in, const int* in_sizes, int n_in,
                              void* d_out, int out_size) {
    const float* h    = (const float*)d_in[0];
    const int*   srcI = (const int*)d_in[1];
    const int*   dstI = (const int*)d_in[2];
    const float* ln_w = (const float*)d_in[3];
    const float* ln_b = (const float*)d_in[4];
    const float* Wv   = (const float*)d_in[5];
    const float* bv   = (const float*)d_in[6];
    const float* W1   = (const float*)d_in[7];
    const float* b1   = (const float*)d_in[8];
    const float* W2   = (const float*)d_in[9];
    const float* b2   = (const float*)d_in[10];
    float* out = (float*)d_out;

    cudaFuncSetAttribute(gemm_ln_kernel, cudaFuncAttributeMaxDynamicSharedMemorySize, GEMM_SMEM);

    prep_kernel<<<(D * NCAT + 255) / 256, 256>>>(Wv, bv, W1, b1, srcI, dstI);
    gemm_ln_kernel<<<M_TOTAL / MT, 256, GEMM_SMEM>>>(h, ln_w, ln_b);
    edge_kernel<<<NB / EBPC, 512>>>(h, srcI, dstI, W2, b2, out);
}

// round 10
// speedup vs baseline: 1.7342x; 1.0377x over previous
#include <cuda_runtime.h>
#include <cuda_fp16.h>
#include <cstdint>

#define NN 21
#define D 256
#define GH 512
#define NE 40
#define NB 8192
#define M_TOTAL (NB * NN)     /* 172032 */
#define NCAT 1280
#define NT8 (NCAT / 8)        /* 160 col-tiles per 8-row group */
#define LN_EPS 1e-5f

#define MT 64                 /* M per CTA (2 CTAs per SM) */
#define NTC 256               /* N chunk */
#define KC 64                 /* K per B stage */
#define NITER 20              /* 5 chunks x 4 k-steps */

#define A_STRH 264
#define B_STRH 72
#define B_STAGE_H (NTC * B_STRH)
#define SZ_A (MT * A_STRH * 2)                   /* 33792 B */
#define GEMM_SMEM (SZ_A + 2 * B_STAGE_H * 2)     /* 107520 B -> 2 CTAs/SM */

#define EBPC 2

// ---------------- scratch ----------------
/* Y in 8x8 tiled layout: half index = ((r>>3)*NT8 + (c>>3))*64 + (r&7)*8 + (c&7) */
__device__ __half g_Y[(size_t)M_TOTAL * NCAT];
__device__ __half g_WcatT[(size_t)NCAT * D];
__device__ float  g_bias[NCAT];
__device__ int    g_bStart[NN + 1];
__device__ int    g_bEdge[NE];

// ---------------- helpers ----------------
__device__ __forceinline__ void cp_async16(void* smem, const void* gmem) {
    unsigned s = (unsigned)__cvta_generic_to_shared(smem);
    asm volatile("cp.async.cg.shared.global [%0], [%1], 16;\n" :: "r"(s), "l"(gmem));
}
__device__ __forceinline__ float gelu1(float t) {
    return 0.5f * t * (1.f + erff(t * 0.7071067811865476f));
}
__device__ __forceinline__ void mma16(float* d, const unsigned* a, const unsigned* b) {
    asm volatile(
        "mma.sync.aligned.m16n8k16.row.col.f32.f16.f16.f32 "
        "{%0,%1,%2,%3}, {%4,%5,%6,%7}, {%8,%9}, {%0,%1,%2,%3};\n"
        : "+f"(d[0]), "+f"(d[1]), "+f"(d[2]), "+f"(d[3])
        : "r"(a[0]), "r"(a[1]), "r"(a[2]), "r"(a[3]), "r"(b[0]), "r"(b[1]));
}
__device__ __forceinline__ void ldsm4(unsigned* r, uint32_t addr) {
    asm volatile("ldmatrix.sync.aligned.m8n8.x4.shared.b16 {%0,%1,%2,%3}, [%4];"
        : "=r"(r[0]), "=r"(r[1]), "=r"(r[2]), "=r"(r[3]) : "r"(addr));
}

// ---------------- kernel 0 ----------------
__global__ void prep_kernel(const float* __restrict__ Wv, const float* __restrict__ bv,
                            const float* __restrict__ W1, const float* __restrict__ b1,
                            const int* __restrict__ srcI, const int* __restrict__ dstI) {
    int idx = blockIdx.x * blockDim.x + threadIdx.x;
    if (idx < D * NCAT) {
        int k = idx / NCAT, n = idx % NCAT;
        float w;
        if (n < 256)      w = Wv[k * 256 + n];
        else if (n < 768) w = W1[k * 512 + (n - 256)];
        else              w = W1[(256 + k) * 512 + (n - 768)];
        g_WcatT[(size_t)n * D + k] = __float2half_rn(w);
    }
    if (idx < NCAT)
        g_bias[idx] = (idx < 256) ? bv[idx] : (idx < 768 ? b1[idx - 256] : 0.f);
    if (blockIdx.x == 0 && threadIdx.x == 0) {
        int cnt[NN];
        for (int n = 0; n < NN; n++) cnt[n] = 0;
        for (int e = 0; e < NE; e++) cnt[dstI[e]]++;
        g_bStart[0] = 0;
        for (int n = 0; n < NN; n++) g_bStart[n + 1] = g_bStart[n] + cnt[n];
        int pos[NN];
        for (int n = 0; n < NN; n++) pos[n] = g_bStart[n];
        for (int e = 0; e < NE; e++) g_bEdge[pos[dstI[e]]++] = e;
    }
}

// ---------------- kernel 1: fused LN + fp16 GEMM ----------------
__device__ __forceinline__ void load_B_stage(__half* sB, int tid, int idx) {
    int nb = (idx >> 2) * NTC, kb = (idx & 3) * KC;
    __half* Bst = sB + (idx & 1) * B_STAGE_H;
    #pragma unroll
    for (int t = 0; t < 8; t++) {
        int ch = tid + (t << 8);
        int row = ch >> 3, c8 = (ch & 7) * 8;
        cp_async16((char*)Bst + row * (B_STRH * 2) + c8 * 2,
                   g_WcatT + (size_t)(nb + row) * D + kb + c8);
    }
    asm volatile("cp.async.commit_group;\n");
}

__global__ __launch_bounds__(256, 2) void gemm_ln_kernel(
    const float* __restrict__ h, const float* __restrict__ lnw, const float* __restrict__ lnb) {
    extern __shared__ __align__(16) char smem[];
    __half* sA = (__half*)smem;
    __half* sB = (__half*)(smem + SZ_A);
    const int tid = threadIdx.x, warp = tid >> 5, lane = tid & 31;
    const int wm = warp & 1, wn = warp >> 1;
    const int gq = lane >> 2, t = lane & 3;
    const int mBase = blockIdx.x * MT;
    const uint32_t sAu = (uint32_t)__cvta_generic_to_shared(sA);
    const uint32_t sBu = (uint32_t)__cvta_generic_to_shared(sB);

    load_B_stage(sB, tid, 0);

    /* fused LayerNorm */
    {
        float4 w0 = ((const float4*)lnw)[2 * lane], w1 = ((const float4*)lnw)[2 * lane + 1];
        float4 bb0 = ((const float4*)lnb)[2 * lane], bb1 = ((const float4*)lnb)[2 * lane + 1];
        #pragma unroll 1
        for (int it = 0; it < 8; it++) {
            int row = warp * 8 + it;
            const float4* r4 = (const float4*)(h + (size_t)(mBase + row) * D);
            float4 va = r4[2 * lane], vb = r4[2 * lane + 1];
            float s = va.x + va.y + va.z + va.w + vb.x + vb.y + vb.z + vb.w;
            float q = va.x*va.x + va.y*va.y + va.z*va.z + va.w*va.w
                    + vb.x*vb.x + vb.y*vb.y + vb.z*vb.z + vb.w*vb.w;
            #pragma unroll
            for (int off = 16; off; off >>= 1) {
                s += __shfl_xor_sync(0xffffffffu, s, off);
                q += __shfl_xor_sync(0xffffffffu, q, off);
            }
            float mu = s * (1.f / D);
            float var = q * (1.f / D) - mu * mu;
            float inv = rsqrtf(var + LN_EPS);
            __half2 h0 = __floats2half2_rn((va.x - mu) * inv * w0.x + bb0.x,
                                           (va.y - mu) * inv * w0.y + bb0.y);
            __half2 h1 = __floats2half2_rn((va.z - mu) * inv * w0.z + bb0.z,
                                           (va.w - mu) * inv * w0.w + bb0.w);
            __half2 h2 = __floats2half2_rn((vb.x - mu) * inv * w1.x + bb1.x,
                                           (vb.y - mu) * inv * w1.y + bb1.y);
            __half2 h3 = __floats2half2_rn((vb.z - mu) * inv * w1.z + bb1.z,
                                           (vb.w - mu) * inv * w1.w + bb1.w);
            uint4 o;
            o.x = *(unsigned*)&h0; o.y = *(unsigned*)&h1;
            o.z = *(unsigned*)&h2; o.w = *(unsigned*)&h3;
            *(uint4*)(sA + row * A_STRH + lane * 8) = o;
        }
    }
    __syncthreads();

    const int lm = lane >> 3, lr = lane & 7;
    uint32_t aBase[2], bOff[4];
    #pragma unroll
    for (int mi = 0; mi < 2; mi++)
        aBase[mi] = sAu + (uint32_t)(((wm * 32 + mi * 16 + (lm & 1) * 8 + lr) * A_STRH
                                      + (lm >> 1) * 8) * 2);
    #pragma unroll
    for (int nj = 0; nj < 4; nj++)
        bOff[nj] = (uint32_t)(((wn * 64 + nj * 16 + (lm >> 1) * 8 + lr) * B_STRH
                               + (lm & 1) * 8) * 2);

    float c[2][8][4];
    for (int i = 0; i < NITER; i++) {
        int chunk = i >> 2, kc = i & 3;
        if (kc == 0) {
            #pragma unroll
            for (int mi = 0; mi < 2; mi++)
                #pragma unroll
                for (int ni = 0; ni < 8; ni++)
                    #pragma unroll
                    for (int j = 0; j < 4; j++) c[mi][ni][j] = 0.f;
        }
        if (i + 1 < NITER) {
            load_B_stage(sB, tid, i + 1);
            asm volatile("cp.async.wait_group 1;\n" ::: "memory");
        } else {
            asm volatile("cp.async.wait_group 0;\n" ::: "memory");
        }
        __syncthreads();

        uint32_t stB = sBu + (uint32_t)((i & 1) * B_STAGE_H * 2);
        #pragma unroll
        for (int ks = 0; ks < 4; ks++) {
            unsigned af[2][4], bf[4][4];
            uint32_t ka = (uint32_t)((kc * KC + ks * 16) * 2);
            uint32_t kb = (uint32_t)((ks * 16) * 2);
            ldsm4(af[0], aBase[0] + ka);
            ldsm4(af[1], aBase[1] + ka);
            ldsm4(bf[0], stB + bOff[0] + kb);
            ldsm4(bf[1], stB + bOff[1] + kb);
            ldsm4(bf[2], stB + bOff[2] + kb);
            ldsm4(bf[3], stB + bOff[3] + kb);
            #pragma unroll
            for (int mi = 0; mi < 2; mi++)
                #pragma unroll
                for (int nj = 0; nj < 4; nj++) {
                    mma16(c[mi][2 * nj],     af[mi], &bf[nj][0]);
                    mma16(c[mi][2 * nj + 1], af[mi], &bf[nj][2]);
                }
        }

        if (kc == 3) {  /* epilogue: bias + tiled coalesced fp16 store */
            int nBase = chunk * NTC;
            #pragma unroll
            for (int mi = 0; mi < 2; mi++)
                #pragma unroll
                for (int ni = 0; ni < 8; ni++) {
                    int r0 = mBase + wm * 32 + mi * 16 + gq;    /* r0&7 == gq */
                    int cT = nBase + wn * 64 + ni * 8;          /* tile-aligned col */
                    int cb = cT + 2 * t;
                    float b0v = g_bias[cb], b1v = g_bias[cb + 1];
                    size_t off = ((size_t)(r0 >> 3) * NT8 + (cT >> 3)) * 64 + gq * 8 + 2 * t;
                    *(__half2*)(g_Y + off) =
                        __floats2half2_rn(c[mi][ni][0] + b0v, c[mi][ni][1] + b1v);
                    *(__half2*)(g_Y + off + (size_t)NT8 * 64) =   /* row r0+8 -> next R */
                        __floats2half2_rn(c[mi][ni][2] + b0v, c[mi][ni][3] + b1v);
                }
        }
        __syncthreads();
    }
}

// ---------------- kernel 2: gates + scatter + residual (tiled-Y aware) ----------------
__global__ __launch_bounds__(512) void edge_kernel(const float* __restrict__ h,
                                                   const int* __restrict__ srcI,
                                                   const int* __restrict__ dstI,
                                                   const float* __restrict__ W2,
                                                   const float* __restrict__ b2,
                                                   float* __restrict__ out) {
    __shared__ __half sV[EBPC * NN * D];
    __shared__ float  sGate[EBPC * NE];
    __shared__ float  sW2[GH];
    __shared__ int sSrc[NE], sDst[NE], sBS[NN + 1], sBE[NE];
    int b0 = blockIdx.x * EBPC;
    int tid = threadIdx.x;
    if (tid < NE) { sSrc[tid] = srcI[tid]; sDst[tid] = dstI[tid]; sBE[tid] = g_bEdge[tid]; }
    if (tid >= 64 && tid < 64 + NN + 1) sBS[tid - 64] = g_bStart[tid - 64];
    if (tid >= 128 && tid < 256) ((float4*)sW2)[tid - 128] = ((const float4*)W2)[tid - 128];
    const uint4* Yq = (const uint4*)g_Y;     /* uint4 idx = (R*NT8 + T)*8 + (r&7) */
    #pragma unroll 1
    for (int i = tid; i < EBPC * NN * 32; i += 512) {   /* V part -> sV (row-major) */
        int r = i >> 5, cc = i & 31;                    /* T = cc (cols 0..255) */
        int gr = b0 * NN + r;
        ((uint4*)sV)[i] = Yq[((size_t)(gr >> 3) * NT8 + cc) * 8 + (gr & 7)];
    }
    __syncthreads();

    int warp = tid >> 5, lane = tid & 31;
    float b2v = __ldg(b2);
    #pragma unroll 1
    for (int kk = 0; kk < 5; kk++) {
        int combo = warp + (kk << 4);
        int be = combo / NE, e = combo - be * NE;
        int gS = (b0 + be) * NN + sSrc[e];
        int gD = (b0 + be) * NN + sDst[e];
        size_t baseS = (size_t)(gS >> 3) * NT8 * 8 + (gS & 7);
        size_t baseD = (size_t)(gD >> 3) * NT8 * 8 + (gD & 7);
        float sum = 0.f;
        #pragma unroll
        for (int i = lane; i < 64; i += 32) {           /* i = 8-col block of gate pair */
            uint4 ua = __ldg(Yq + baseS + (size_t)(32 + i) * 8);   /* A: cols 256.. T=32+i */
            uint4 ub = __ldg(Yq + baseD + (size_t)(96 + i) * 8);   /* B: cols 768.. T=96+i */
            const float* wv = sW2 + i * 8;
            float2 a0 = __half22float2(*(__half2*)&ua.x), d0 = __half22float2(*(__half2*)&ub.x);
            float2 a1 = __half22float2(*(__half2*)&ua.y), d1 = __half22float2(*(__half2*)&ub.y);
            float2 a2 = __half22float2(*(__half2*)&ua.z), d2 = __half22float2(*(__half2*)&ub.z);
            float2 a3 = __half22float2(*(__half2*)&ua.w), d3 = __half22float2(*(__half2*)&ub.w);
            sum += gelu1(a0.x + d0.x) * wv[0] + gelu1(a0.y + d0.y) * wv[1];
            sum += gelu1(a1.x + d1.x) * wv[2] + gelu1(a1.y + d1.y) * wv[3];
            sum += gelu1(a2.x + d2.x) * wv[4] + gelu1(a2.y + d2.y) * wv[5];
            sum += gelu1(a3.x + d3.x) * wv[6] + gelu1(a3.y + d3.y) * wv[7];
        }
        #pragma unroll
        for (int off = 16; off; off >>= 1) sum += __shfl_xor_sync(0xffffffffu, sum, off);
        if (!lane) sGate[combo] = 1.f / (1.f + __expf(-(sum + b2v)));
    }
    __syncthreads();

    const float* hb = h + (size_t)b0 * NN * D;
    float* ob = out + (size_t)b0 * NN * D;
    int col = tid & 63, slot = tid >> 6;
    #pragma unroll 1
    for (int task = slot; task < EBPC * NN; task += 8) {
        int be = task / NN, n = task - be * NN;
        int r = be * NN + n;
        float4 acc = ((const float4*)(hb + r * D))[col];
        int jEnd = sBS[n + 1];
        for (int jj = sBS[n]; jj < jEnd; jj++) {
            int e = sBE[jj];
            float gte = sGate[be * NE + e];
            uint2 u = *(const uint2*)(sV + (be * NN + sSrc[e]) * D + col * 4);
            float2 lo = __half22float2(*(__half2*)&u.x);
            float2 hi = __half22float2(*(__half2*)&u.y);
            acc.x += gte * lo.x; acc.y += gte * lo.y;
            acc.z += gte * hi.x; acc.w += gte * hi.y;
        }
        ((float4*)(ob + r * D))[col] = acc;
    }
}

// ---------------- launcher ----------------
extern "C" void kernel_launch(void* const* d_in, const int* in_sizes, int n_in,
                              void* d_out, int out_size) {
    const float* h    = (const float*)d_in[0];
    const int*   srcI = (const int*)d_in[1];
    const int*   dstI = (const int*)d_in[2];
    const float* ln_w = (const float*)d_in[3];
    const float* ln_b = (const float*)d_in[4];
    const float* Wv   = (const float*)d_in[5];
    const float* bv   = (const float*)d_in[6];
    const float* W1   = (const float*)d_in[7];
    const float* b1   = (const float*)d_in[8];
    const float* W2   = (const float*)d_in[9];
    const float* b2   = (const float*)d_in[10];
    float* out = (float*)d_out;

    cudaFuncSetAttribute(gemm_ln_kernel, cudaFuncAttributeMaxDynamicSharedMemorySize, GEMM_SMEM);

    prep_kernel<<<(D * NCAT + 255) / 256, 256>>>(Wv, bv, W1, b1, srcI, dstI);
    gemm_ln_kernel<<<M_TOTAL / MT, 256, GEMM_SMEM>>>(h, ln_w, ln_b);
    edge_kernel<<<NB / EBPC, 512>>>(h, srcI, dstI, W2, b2, out);
}

// round 11
// speedup vs baseline: 1.8436x; 1.0631x over previous
#include <cuda_runtime.h>
#include <cuda_fp16.h>
#include <cstdint>

#define NN 21
#define D 256
#define GH 512
#define NE 40
#define NB 8192
#define M_TOTAL (NB * NN)     /* 172032 */
#define NCAT 1280
#define NT8 (NCAT / 8)        /* 160 col-tiles per 8-row group */
#define LN_EPS 1e-5f

#define MT 64                 /* M per CTA (2 CTAs per SM) */
#define NTC 256               /* N chunk */
#define KC 64                 /* K per B stage */
#define NITER 20              /* 5 chunks x 4 k-steps */

#define A_STRH 264
#define B_STRH 72
#define B_STAGE_H (NTC * B_STRH)
#define SZ_A (MT * A_STRH * 2)                   /* 33792 B */
#define GEMM_SMEM (SZ_A + 2 * B_STAGE_H * 2)     /* 107520 B -> 2 CTAs/SM */

#define EBPC 2

// ---------------- scratch ----------------
/* Y tiled: half index = ((r>>3)*NT8 + (c>>3))*64 + (r&7)*8 + (c&7) */
__device__ __half g_Y[(size_t)M_TOTAL * NCAT];
__device__ __half g_WcatT[(size_t)NCAT * D];
__device__ float  g_bias[NCAT];
__device__ int    g_bStart[NN + 1];
__device__ int    g_bEdge[NE];

// ---------------- helpers ----------------
__device__ __forceinline__ void cp_async16(void* smem, const void* gmem) {
    unsigned s = (unsigned)__cvta_generic_to_shared(smem);
    asm volatile("cp.async.cg.shared.global [%0], [%1], 16;\n" :: "r"(s), "l"(gmem));
}
/* tanh-form gelu (max abs dev from exact ~6e-4; cheap MUFU path) */
__device__ __forceinline__ float gelu_t(float x) {
    float u = 0.7978845608f * fmaf(0.044715f * x, x * x, x);
    float e = __expf(2.f * u);
    float th = 1.f - __fdividef(2.f, e + 1.f);
    return 0.5f * x * (1.f + th);
}
__device__ __forceinline__ void mma16(float* d, const unsigned* a, const unsigned* b) {
    asm volatile(
        "mma.sync.aligned.m16n8k16.row.col.f32.f16.f16.f32 "
        "{%0,%1,%2,%3}, {%4,%5,%6,%7}, {%8,%9}, {%0,%1,%2,%3};\n"
        : "+f"(d[0]), "+f"(d[1]), "+f"(d[2]), "+f"(d[3])
        : "r"(a[0]), "r"(a[1]), "r"(a[2]), "r"(a[3]), "r"(b[0]), "r"(b[1]));
}
__device__ __forceinline__ void ldsm4(unsigned* r, uint32_t addr) {
    asm volatile("ldmatrix.sync.aligned.m8n8.x4.shared.b16 {%0,%1,%2,%3}, [%4];"
        : "=r"(r[0]), "=r"(r[1]), "=r"(r[2]), "=r"(r[3]) : "r"(addr));
}

// ---------------- kernel 0 ----------------
__global__ void prep_kernel(const float* __restrict__ Wv, const float* __restrict__ bv,
                            const float* __restrict__ W1, const float* __restrict__ b1,
                            const int* __restrict__ srcI, const int* __restrict__ dstI) {
    int idx = blockIdx.x * blockDim.x + threadIdx.x;
    if (idx < D * NCAT) {
        int k = idx / NCAT, n = idx % NCAT;
        float w;
        if (n < 256)      w = Wv[k * 256 + n];
        else if (n < 768) w = W1[k * 512 + (n - 256)];
        else              w = W1[(256 + k) * 512 + (n - 768)];
        g_WcatT[(size_t)n * D + k] = __float2half_rn(w);
    }
    if (idx < NCAT)
        g_bias[idx] = (idx < 256) ? bv[idx] : (idx < 768 ? b1[idx - 256] : 0.f);
    if (blockIdx.x == 0 && threadIdx.x == 0) {
        int cnt[NN];
        for (int n = 0; n < NN; n++) cnt[n] = 0;
        for (int e = 0; e < NE; e++) cnt[dstI[e]]++;
        g_bStart[0] = 0;
        for (int n = 0; n < NN; n++) g_bStart[n + 1] = g_bStart[n] + cnt[n];
        int pos[NN];
        for (int n = 0; n < NN; n++) pos[n] = g_bStart[n];
        for (int e = 0; e < NE; e++) g_bEdge[pos[dstI[e]]++] = e;
    }
}

// ---------------- kernel 1: fused LN + fp16 GEMM ----------------
__device__ __forceinline__ void load_B_stage(__half* sB, int tid, int idx) {
    int nb = (idx >> 2) * NTC, kb = (idx & 3) * KC;
    __half* Bst = sB + (idx & 1) * B_STAGE_H;
    #pragma unroll
    for (int t = 0; t < 8; t++) {
        int ch = tid + (t << 8);
        int row = ch >> 3, c8 = (ch & 7) * 8;
        cp_async16((char*)Bst + row * (B_STRH * 2) + c8 * 2,
                   g_WcatT + (size_t)(nb + row) * D + kb + c8);
    }
    asm volatile("cp.async.commit_group;\n");
}

__global__ __launch_bounds__(256, 2) void gemm_ln_kernel(
    const float* __restrict__ h, const float* __restrict__ lnw, const float* __restrict__ lnb) {
    extern __shared__ __align__(16) char smem[];
    __half* sA = (__half*)smem;
    __half* sB = (__half*)(smem + SZ_A);
    const int tid = threadIdx.x, warp = tid >> 5, lane = tid & 31;
    const int wm = warp & 1, wn = warp >> 1;
    const int gq = lane >> 2, t = lane & 3;
    const int mBase = blockIdx.x * MT;
    const uint32_t sAu = (uint32_t)__cvta_generic_to_shared(sA);
    const uint32_t sBu = (uint32_t)__cvta_generic_to_shared(sB);

    load_B_stage(sB, tid, 0);

    /* fused LayerNorm: warp per row, unroll 2 so loads batch (MLP up) */
    {
        float4 w0 = ((const float4*)lnw)[2 * lane], w1 = ((const float4*)lnw)[2 * lane + 1];
        float4 bb0 = ((const float4*)lnb)[2 * lane], bb1 = ((const float4*)lnb)[2 * lane + 1];
        #pragma unroll 2
        for (int it = 0; it < 8; it++) {
            int row = warp * 8 + it;
            const float4* r4 = (const float4*)(h + (size_t)(mBase + row) * D);
            float4 va = r4[2 * lane], vb = r4[2 * lane + 1];
            float s = va.x + va.y + va.z + va.w + vb.x + vb.y + vb.z + vb.w;
            float q = va.x*va.x + va.y*va.y + va.z*va.z + va.w*va.w
                    + vb.x*vb.x + vb.y*vb.y + vb.z*vb.z + vb.w*vb.w;
            #pragma unroll
            for (int off = 16; off; off >>= 1) {
                s += __shfl_xor_sync(0xffffffffu, s, off);
                q += __shfl_xor_sync(0xffffffffu, q, off);
            }
            float mu = s * (1.f / D);
            float var = q * (1.f / D) - mu * mu;
            float inv = rsqrtf(var + LN_EPS);
            __half2 h0 = __floats2half2_rn((va.x - mu) * inv * w0.x + bb0.x,
                                           (va.y - mu) * inv * w0.y + bb0.y);
            __half2 h1 = __floats2half2_rn((va.z - mu) * inv * w0.z + bb0.z,
                                           (va.w - mu) * inv * w0.w + bb0.w);
            __half2 h2 = __floats2half2_rn((vb.x - mu) * inv * w1.x + bb1.x,
                                           (vb.y - mu) * inv * w1.y + bb1.y);
            __half2 h3 = __floats2half2_rn((vb.z - mu) * inv * w1.z + bb1.z,
                                           (vb.w - mu) * inv * w1.w + bb1.w);
            uint4 o;
            o.x = *(unsigned*)&h0; o.y = *(unsigned*)&h1;
            o.z = *(unsigned*)&h2; o.w = *(unsigned*)&h3;
            *(uint4*)(sA + row * A_STRH + lane * 8) = o;
        }
    }
    __syncthreads();

    const int lm = lane >> 3, lr = lane & 7;
    uint32_t aBase[2], bOff[4];
    #pragma unroll
    for (int mi = 0; mi < 2; mi++)
        aBase[mi] = sAu + (uint32_t)(((wm * 32 + mi * 16 + (lm & 1) * 8 + lr) * A_STRH
                                      + (lm >> 1) * 8) * 2);
    #pragma unroll
    for (int nj = 0; nj < 4; nj++)
        bOff[nj] = (uint32_t)(((wn * 64 + nj * 16 + (lm >> 1) * 8 + lr) * B_STRH
                               + (lm & 1) * 8) * 2);

    float c[2][8][4];
    for (int i = 0; i < NITER; i++) {
        int chunk = i >> 2, kc = i & 3;
        if (kc == 0) {
            #pragma unroll
            for (int mi = 0; mi < 2; mi++)
                #pragma unroll
                for (int ni = 0; ni < 8; ni++)
                    #pragma unroll
                    for (int j = 0; j < 4; j++) c[mi][ni][j] = 0.f;
        }
        if (i + 1 < NITER) {
            load_B_stage(sB, tid, i + 1);
            asm volatile("cp.async.wait_group 1;\n" ::: "memory");
        } else {
            asm volatile("cp.async.wait_group 0;\n" ::: "memory");
        }
        __syncthreads();

        uint32_t stB = sBu + (uint32_t)((i & 1) * B_STAGE_H * 2);
        #pragma unroll
        for (int ks = 0; ks < 4; ks++) {
            unsigned af[2][4], bf[4][4];
            uint32_t ka = (uint32_t)((kc * KC + ks * 16) * 2);
            uint32_t kb = (uint32_t)((ks * 16) * 2);
            ldsm4(af[0], aBase[0] + ka);
            ldsm4(af[1], aBase[1] + ka);
            ldsm4(bf[0], stB + bOff[0] + kb);
            ldsm4(bf[1], stB + bOff[1] + kb);
            ldsm4(bf[2], stB + bOff[2] + kb);
            ldsm4(bf[3], stB + bOff[3] + kb);
            #pragma unroll
            for (int mi = 0; mi < 2; mi++)
                #pragma unroll
                for (int nj = 0; nj < 4; nj++) {
                    mma16(c[mi][2 * nj],     af[mi], &bf[nj][0]);
                    mma16(c[mi][2 * nj + 1], af[mi], &bf[nj][2]);
                }
        }

        if (kc == 3) {  /* epilogue: bias + tiled coalesced fp16 store */
            int nBase = chunk * NTC;
            #pragma unroll
            for (int mi = 0; mi < 2; mi++)
                #pragma unroll
                for (int ni = 0; ni < 8; ni++) {
                    int r0 = mBase + wm * 32 + mi * 16 + gq;
                    int cT = nBase + wn * 64 + ni * 8;
                    int cb = cT + 2 * t;
                    float b0v = g_bias[cb], b1v = g_bias[cb + 1];
                    size_t off = ((size_t)(r0 >> 3) * NT8 + (cT >> 3)) * 64 + gq * 8 + 2 * t;
                    *(__half2*)(g_Y + off) =
                        __floats2half2_rn(c[mi][ni][0] + b0v, c[mi][ni][1] + b1v);
                    *(__half2*)(g_Y + off + (size_t)NT8 * 64) =
                        __floats2half2_rn(c[mi][ni][2] + b0v, c[mi][ni][3] + b1v);
                }
        }
        __syncthreads();
    }
}

// ---------------- kernel 2: gates + scatter + residual ----------------
__global__ __launch_bounds__(512) void edge_kernel(const float* __restrict__ h,
                                                   const int* __restrict__ srcI,
                                                   const int* __restrict__ dstI,
                                                   const float* __restrict__ W2,
                                                   const float* __restrict__ b2,
                                                   float* __restrict__ out) {
    __shared__ __half sV[EBPC * NN * D];
    __shared__ float  sGate[EBPC * NE];
    __shared__ float  sW2[GH];
    __shared__ int sSrc[NE], sDst[NE], sBS[NN + 1], sBE[NE];
    int b0 = blockIdx.x * EBPC;
    int tid = threadIdx.x;
    if (tid < NE) { sSrc[tid] = srcI[tid]; sDst[tid] = dstI[tid]; sBE[tid] = g_bEdge[tid]; }
    if (tid >= 64 && tid < 64 + NN + 1) sBS[tid - 64] = g_bStart[tid - 64];
    if (tid >= 128 && tid < 256) ((float4*)sW2)[tid - 128] = ((const float4*)W2)[tid - 128];
    const uint4* Yq = (const uint4*)g_Y;
    #pragma unroll 1
    for (int i = tid; i < EBPC * NN * 32; i += 512) {
        int r = i >> 5, cc = i & 31;
        int gr = b0 * NN + r;
        ((uint4*)sV)[i] = Yq[((size_t)(gr >> 3) * NT8 + cc) * 8 + (gr & 7)];
    }
    __syncthreads();

    int warp = tid >> 5, lane = tid & 31;
    float b2v = __ldg(b2);
    #pragma unroll 1
    for (int kk = 0; kk < 5; kk++) {
        int combo = warp + (kk << 4);
        int be = combo / NE, e = combo - be * NE;
        int gS = (b0 + be) * NN + sSrc[e];
        int gD = (b0 + be) * NN + sDst[e];
        size_t baseS = (size_t)(gS >> 3) * NT8 * 8 + (gS & 7);
        size_t baseD = (size_t)(gD >> 3) * NT8 * 8 + (gD & 7);
        float sum = 0.f;
        #pragma unroll
        for (int i = lane; i < 64; i += 32) {
            uint4 ua = __ldg(Yq + baseS + (size_t)(32 + i) * 8);
            uint4 ub = __ldg(Yq + baseD + (size_t)(96 + i) * 8);
            const float* wv = sW2 + i * 8;
            __half2 t0 = __hadd2(*(__half2*)&ua.x, *(__half2*)&ub.x);
            __half2 t1 = __hadd2(*(__half2*)&ua.y, *(__half2*)&ub.y);
            __half2 t2 = __hadd2(*(__half2*)&ua.z, *(__half2*)&ub.z);
            __half2 t3 = __hadd2(*(__half2*)&ua.w, *(__half2*)&ub.w);
            float2 f0 = __half22float2(t0), f1 = __half22float2(t1);
            float2 f2 = __half22float2(t2), f3 = __half22float2(t3);
            sum += gelu_t(f0.x) * wv[0] + gelu_t(f0.y) * wv[1];
            sum += gelu_t(f1.x) * wv[2] + gelu_t(f1.y) * wv[3];
            sum += gelu_t(f2.x) * wv[4] + gelu_t(f2.y) * wv[5];
            sum += gelu_t(f3.x) * wv[6] + gelu_t(f3.y) * wv[7];
        }
        #pragma unroll
        for (int off = 16; off; off >>= 1) sum += __shfl_xor_sync(0xffffffffu, sum, off);
        if (!lane) sGate[combo] = 1.f / (1.f + __expf(-(sum + b2v)));
    }
    __syncthreads();

    const float* hb = h + (size_t)b0 * NN * D;
    float* ob = out + (size_t)b0 * NN * D;
    int col = tid & 63, slot = tid >> 6;
    #pragma unroll 1
    for (int task = slot; task < EBPC * NN; task += 8) {
        int be = task / NN, n = task - be * NN;
        int r = be * NN + n;
        float4 acc = ((const float4*)(hb + r * D))[col];
        int jEnd = sBS[n + 1];
        for (int jj = sBS[n]; jj < jEnd; jj++) {
            int e = sBE[jj];
            float gte = sGate[be * NE + e];
            uint2 u = *(const uint2*)(sV + (be * NN + sSrc[e]) * D + col * 4);
            float2 lo = __half22float2(*(__half2*)&u.x);
            float2 hi = __half22float2(*(__half2*)&u.y);
            acc.x += gte * lo.x; acc.y += gte * lo.y;
            acc.z += gte * hi.x; acc.w += gte * hi.y;
        }
        ((float4*)(ob + r * D))[col] = acc;
    }
}

// ---------------- launcher ----------------
extern "C" void kernel_launch(void* const* d_in, const int* in_sizes, int n_in,
                              void* d_out, int out_size) {
    const float* h    = (const float*)d_in[0];
    const int*   srcI = (const int*)d_in[1];
    const int*   dstI = (const int*)d_in[2];
    const float* ln_w = (const float*)d_in[3];
    const float* ln_b = (const float*)d_in[4];
    const float* Wv   = (const float*)d_in[5];
    const float* bv   = (const float*)d_in[6];
    const float* W1   = (const float*)d_in[7];
    const float* b1   = (const float*)d_in[8];
    const float* W2   = (const float*)d_in[9];
    const float* b2   = (const float*)d_in[10];
    float* out = (float*)d_out;

    cudaFuncSetAttribute(gemm_ln_kernel, cudaFuncAttributeMaxDynamicSharedMemorySize, GEMM_SMEM);

    prep_kernel<<<(D * NCAT + 255) / 256, 256>>>(Wv, bv, W1, b1, srcI, dstI);
    gemm_ln_kernel<<<M_TOTAL / MT, 256, GEMM_SMEM>>>(h, ln_w, ln_b);
    edge_kernel<<<NB / EBPC, 512>>>(h, srcI, dstI, W2, b2, out);
}